// round 7
// baseline (speedup 1.0000x reference)
#include <cuda_runtime.h>
#include <cuda_fp16.h>
#include <cstdint>

// ---------------------------------------------------------------------------
// W4A16 grouped GEMM: out[32,28672] = x[32,8192] @ dequant(qweight) + bias
//   qweight int32 [K/8, N] : 8 int4 nibbles per word along K, zero-point 8
//   scales  fp16-origin [K/128, N]
//
// HARNESS CONTRACT (deduced R5/R6): fp16 tensors are delivered upcast to
// float32 (element counts unchanged); output buffer is float32. So x, scales,
// bias are read as float and converted (losslessly) to fp16 in registers;
// results are rounded through fp16 (dot first, then +bias, matching jnp
// rounding order) and stored as f32.
//
// Compute: mma.sync.m16n8k16.row.col.f32.f16.f16.f32 + ldmatrix
// (tcgen05 is compute_103a-gated and unavailable in this toolchain).
//
// CTA = 128 threads (4 warps) x 128 n-columns; warp owns 32 n.
// K chunk = 64, double-buffered SMEM, register prefetch of next chunk's LDGs.
// Inputs resolved by unique element count:
//   x = 262144, qweight = 29360128, scales = 1835008, bias = 28672.
// ---------------------------------------------------------------------------

static constexpr int MDIM    = 32;
static constexpr int KDIM    = 8192;
static constexpr int NDIM    = 28672;
static constexpr int NT      = 128;             // n per CTA
static constexpr int KC      = 64;              // k per chunk
static constexpr int NCHUNK  = KDIM / KC;       // 128
static constexpr int THREADS = 128;
static constexpr int XSTRIDE = 144;             // bytes per x row in SMEM (pad)

// --------------------------- PTX helpers -----------------------------------

__device__ __forceinline__ uint32_t smem_u32(const void* p) {
    uint32_t a;
    asm("{ .reg .u64 t; cvta.to.shared.u64 t, %1; cvt.u32.u64 %0, t; }"
        : "=r"(a) : "l"(p));
    return a;
}

__device__ __forceinline__ void ldmatrix_x4(uint32_t* r, uint32_t addr) {
    asm volatile(
        "ldmatrix.sync.aligned.m8n8.x4.shared.b16 {%0,%1,%2,%3}, [%4];"
        : "=r"(r[0]), "=r"(r[1]), "=r"(r[2]), "=r"(r[3]) : "r"(addr));
}

__device__ __forceinline__ void mma_16816(float* c, const uint32_t* a,
                                          uint32_t b0, uint32_t b1) {
    asm volatile(
        "mma.sync.aligned.m16n8k16.row.col.f32.f16.f16.f32 "
        "{%0,%1,%2,%3}, {%4,%5,%6,%7}, {%8,%9}, {%0,%1,%2,%3};"
        : "+f"(c[0]), "+f"(c[1]), "+f"(c[2]), "+f"(c[3])
        : "r"(a[0]), "r"(a[1]), "r"(a[2]), "r"(a[3]), "r"(b0), "r"(b1));
}

__device__ __forceinline__ uint32_t pack_h2(float a, float b) {
    __half2 h = __floats2half2_rn(a, b);
    return *reinterpret_cast<uint32_t*>(&h);
}

// --------------------------- dequant ---------------------------------------
// Word w packs 8 int4 along k (nibble j = k offset j). Byte t holds the pair
// (k=2t low nibble, k=2t+1 high nibble). Magic fp16 construction:
//   replicate byte t into bytes 0 and 2 (byte_perm), mask 0x00F0000F, OR 0x6400:
//     lo half = 1024 + n_lo          hi half = 1024 + 16*n_hi
//   hsub2 {1032, 1152} (exact), hmul2 {s, s/16} -> {(n_lo-8)*s, (n_hi-8)*s}
// Single fp16 rounding per weight == reference semantics.
__device__ __forceinline__ uint32_t dq_pair(uint32_t w, uint32_t sel, uint32_t mul2u) {
    const uint32_t SUBC = 0x64806408u;  // half2 {1032, 1152}
    uint32_t v = __byte_perm(w, 0, sel);
    uint32_t p = (v & 0x00F0000Fu) | 0x64006400u;
    __half2 h = __hmul2(__hsub2(*reinterpret_cast<__half2*>(&p),
                                *reinterpret_cast<const __half2*>(&SUBC)),
                        *reinterpret_cast<__half2*>(&mul2u));
    return *reinterpret_cast<uint32_t*>(&h);
}

// --------------------------- prefetch fragment ------------------------------

struct Frag {
    uint4  qa, qb;           // 8 qweight words: row c*8+(tid>>4), word cols (tid&15)*4, +64
    float4 xa0, xa1;         // x row (tid>>3),    k = c*64 + (tid&7)*8 .. +7
    float4 xb0, xb1;         // x row (tid>>3)+16, same k
    float  sc;               // scales[c/2][n0+tid] (f32 on the wire)
};

__device__ __forceinline__ Frag load_frag(int c, const uint4* __restrict__ qw4,
                                          const float4* __restrict__ x4,
                                          const float* __restrict__ scales,
                                          int tid, int n0) {
    Frag f;
    int qi = (c * 8 + (tid >> 4)) * (NDIM / 4) + (n0 >> 2) + (tid & 15);
    f.qa = qw4[qi];
    f.qb = qw4[qi + 16];
    int xi = (tid >> 3) * (KDIM / 4) + c * 16 + (tid & 7) * 2;
    f.xa0 = x4[xi];
    f.xa1 = x4[xi + 1];
    f.xb0 = x4[xi + 16 * (KDIM / 4)];
    f.xb1 = x4[xi + 16 * (KDIM / 4) + 1];
    f.sc  = scales[(c >> 1) * NDIM + n0 + tid];
    return f;
}

// --------------------------- kernel -----------------------------------------

__global__ void __launch_bounds__(THREADS)
w4a16_hmma_kernel(const float* __restrict__ x,
                  const uint32_t* __restrict__ qweight,
                  const float* __restrict__ scales,
                  const float* __restrict__ bias,
                  float* __restrict__ out) {
    __shared__ uint32_t s_qw[2][8 * 128];                    // raw words [row][n]
    __shared__ __align__(16) uint8_t s_x[2][32 * XSTRIDE];   // x chunk (fp16), padded rows
    __shared__ __half s_sc[2][128];                          // scales row for tile

    const int tid  = threadIdx.x;
    const int lane = tid & 31;
    const int wid  = tid >> 5;
    const int n0   = blockIdx.x * NT;
    const int t4   = lane & 3;
    const uint32_t sel = 0x4040u + (uint32_t)t4 * 0x0101u;   // byte t -> bytes 0,2

    // per-thread n indices inside the CTA tile (4 n8-tiles per warp)
    int nl[4];
#pragma unroll
    for (int j = 0; j < 4; ++j) nl[j] = wid * 32 + (lane >> 2) + 8 * j;

    const uint4*  qw4 = reinterpret_cast<const uint4*>(qweight);
    const float4* x4  = reinterpret_cast<const float4*>(x);
    const __half one16 = __ushort_as_half(0x2C00);           // 1/16

    // SMEM store addresses (chunk-invariant)
    uint32_t* qdst = &s_qw[0][(tid >> 4) * 128 + (tid & 15) * 4];
    uint8_t*  xdst = &s_x[0][(tid >> 3) * XSTRIDE + (tid & 7) * 16];
    const uint32_t xm_base = smem_u32(&s_x[0][0]) +
                             (uint32_t)(lane & 15) * XSTRIDE + (uint32_t)(lane >> 4) * 16;

    float acc[2][4][4];
#pragma unroll
    for (int mt = 0; mt < 2; ++mt)
#pragma unroll
        for (int j = 0; j < 4; ++j)
#pragma unroll
            for (int r = 0; r < 4; ++r) acc[mt][j][r] = 0.0f;

    Frag cur = load_frag(0, qw4, x4, scales, tid, n0);

#pragma unroll 2
    for (int c = 0; c < NCHUNK; ++c) {
        const int buf = c & 1;
        Frag nxt = load_frag((c + 1) & (NCHUNK - 1), qw4, x4, scales, tid, n0);

        // stage current chunk to SMEM (x converted f32 -> fp16, lossless)
        uint32_t* qd = qdst + buf * (8 * 128);
        *reinterpret_cast<uint4*>(qd)      = cur.qa;
        *reinterpret_cast<uint4*>(qd + 64) = cur.qb;
        uint8_t* xd = xdst + buf * (32 * XSTRIDE);
        uint4 hx;
        hx.x = pack_h2(cur.xa0.x, cur.xa0.y); hx.y = pack_h2(cur.xa0.z, cur.xa0.w);
        hx.z = pack_h2(cur.xa1.x, cur.xa1.y); hx.w = pack_h2(cur.xa1.z, cur.xa1.w);
        *reinterpret_cast<uint4*>(xd) = hx;
        hx.x = pack_h2(cur.xb0.x, cur.xb0.y); hx.y = pack_h2(cur.xb0.z, cur.xb0.w);
        hx.z = pack_h2(cur.xb1.x, cur.xb1.y); hx.w = pack_h2(cur.xb1.z, cur.xb1.w);
        *reinterpret_cast<uint4*>(xd + 16 * XSTRIDE) = hx;
        s_sc[buf][tid] = __float2half(cur.sc);
        __syncthreads();

        // per-n-column multipliers {s, s/16}
        uint32_t mul2[4];
#pragma unroll
        for (int j = 0; j < 4; ++j) {
            __half s = s_sc[buf][nl[j]];
            __half2 m = __halves2half2(s, __hmul(s, one16));
            mul2[j] = *reinterpret_cast<uint32_t*>(&m);
        }

        const uint32_t* qs = &s_qw[buf][0];
        const uint32_t xb = xm_base + (uint32_t)buf * (32 * XSTRIDE);

#pragma unroll
        for (int s4 = 0; s4 < 4; ++s4) {            // 4 k16 steps
            uint32_t a0[4], a1[4];
            ldmatrix_x4(a0, xb + s4 * 32);                    // m rows 0-15
            ldmatrix_x4(a1, xb + s4 * 32 + 16 * XSTRIDE);     // m rows 16-31
#pragma unroll
            for (int j = 0; j < 4; ++j) {
                uint32_t w0 = qs[(2 * s4)     * 128 + nl[j]];
                uint32_t w1 = qs[(2 * s4 + 1) * 128 + nl[j]];
                uint32_t b0 = dq_pair(w0, sel, mul2[j]);      // k = 2t, 2t+1
                uint32_t b1 = dq_pair(w1, sel, mul2[j]);      // k = 2t+8, 2t+9
                mma_16816(acc[0][j], a0, b0, b1);
                mma_16816(acc[1][j], a1, b0, b1);
            }
        }
        __syncthreads();
        cur = nxt;
    }

    // ------------------------- epilogue -------------------------------------
    // C fragment: c0,c1 -> (m = mt*16 + lane>>2,   n = base+2t, +1)
    //             c2,c3 -> (m = mt*16 + lane>>2+8, same n)
    // Match jnp rounding order: round dot to f16, add f16 bias (one more f16
    // rounding), upcast to f32 for the store.
#pragma unroll
    for (int j = 0; j < 4; ++j) {
        const int n = n0 + wid * 32 + j * 8 + 2 * t4;
        const float2 bf = *reinterpret_cast<const float2*>(bias + n);
        const __half hbx = __float2half(bf.x);   // lossless (fp16-origin)
        const __half hby = __float2half(bf.y);
#pragma unroll
        for (int mt = 0; mt < 2; ++mt) {
            const int m0 = mt * 16 + (lane >> 2);
            float2 v01, v23;
            v01.x = __half2float(__hadd(__float2half(acc[mt][j][0]), hbx));
            v01.y = __half2float(__hadd(__float2half(acc[mt][j][1]), hby));
            v23.x = __half2float(__hadd(__float2half(acc[mt][j][2]), hbx));
            v23.y = __half2float(__hadd(__float2half(acc[mt][j][3]), hby));
            *reinterpret_cast<float2*>(out + m0 * NDIM + n)       = v01;
            *reinterpret_cast<float2*>(out + (m0 + 8) * NDIM + n) = v23;
        }
    }
}

// --------------------------- launch ------------------------------------------

extern "C" void kernel_launch(void* const* d_in, const int* in_sizes, int n_in,
                              void* d_out, int out_size) {
    (void)out_size;
    // Resolve inputs by unique element counts (robust to metadata ordering).
    const float*    x    = nullptr;   // 32*8192     = 262144   (f32 on wire)
    const uint32_t* qw   = nullptr;   // 1024*28672  = 29360128 (int32)
    const float*    sc   = nullptr;   // 64*28672    = 1835008  (f32 on wire)
    const float*    bias = nullptr;   // 28672                  (f32 on wire)
    for (int i = 0; i < n_in; ++i) {
        switch (in_sizes[i]) {
            case MDIM * KDIM:            x    = (const float*)d_in[i];    break;
            case (KDIM / 8) * NDIM:      qw   = (const uint32_t*)d_in[i]; break;
            case (KDIM / 128) * NDIM:    sc   = (const float*)d_in[i];    break;
            case NDIM:                   bias = (const float*)d_in[i];    break;
            default: break;
        }
    }
    float* out = (float*)d_out;

    w4a16_hmma_kernel<<<NDIM / NT, THREADS>>>(x, qw, sc, bias, out);
}

// round 8
// speedup vs baseline: 1.7926x; 1.7926x over previous
#include <cuda_runtime.h>
#include <cuda_fp16.h>
#include <cstdint>

// ---------------------------------------------------------------------------
// W4A16 grouped GEMM: out[32,28672] = x[32,8192] @ dequant(qweight) + bias
//   qweight int32 [K/8, N] : 8 int4 nibbles per word along K, zero-point 8
//   scales / x / bias: fp16-origin, delivered as float32; output float32.
//
// R7: split-K x8. Grid (224, 8): each CTA computes a 128n x 32m x 1024k
// partial in f32 into device scratch; reduce kernel sums 8 partials, rounds
// the dot through fp16, adds fp16 bias (reference rounding order), stores f32.
// Fixes R6's 9.2% occupancy (224 CTAs -> 1792 CTAs, ~20 warps/SM).
//
// Inner pipeline unchanged: mma.sync.m16n8k16 + ldmatrix, raw qweight words
// LDS-broadcast and dequantized straight into B fragments (byte_perm + LOP3
// magic-bias + exact HSUB2/HMUL2 {s, s/16} -> single fp16 rounding/weight).
// ---------------------------------------------------------------------------

static constexpr int MDIM    = 32;
static constexpr int KDIM    = 8192;
static constexpr int NDIM    = 28672;
static constexpr int NT      = 128;             // n per CTA
static constexpr int KC      = 64;              // k per chunk
static constexpr int KSPLIT  = 8;
static constexpr int CPS     = KDIM / KC / KSPLIT;  // chunks per split = 16
static constexpr int THREADS = 128;
static constexpr int XSTRIDE = 144;             // bytes per x row in SMEM (pad)

__device__ float g_scratch[KSPLIT * MDIM * NDIM];   // 29.36 MB partials

// --------------------------- PTX helpers -----------------------------------

__device__ __forceinline__ uint32_t smem_u32(const void* p) {
    uint32_t a;
    asm("{ .reg .u64 t; cvta.to.shared.u64 t, %1; cvt.u32.u64 %0, t; }"
        : "=r"(a) : "l"(p));
    return a;
}

__device__ __forceinline__ void ldmatrix_x4(uint32_t* r, uint32_t addr) {
    asm volatile(
        "ldmatrix.sync.aligned.m8n8.x4.shared.b16 {%0,%1,%2,%3}, [%4];"
        : "=r"(r[0]), "=r"(r[1]), "=r"(r[2]), "=r"(r[3]) : "r"(addr));
}

__device__ __forceinline__ void mma_16816(float* c, const uint32_t* a,
                                          uint32_t b0, uint32_t b1) {
    asm volatile(
        "mma.sync.aligned.m16n8k16.row.col.f32.f16.f16.f32 "
        "{%0,%1,%2,%3}, {%4,%5,%6,%7}, {%8,%9}, {%0,%1,%2,%3};"
        : "+f"(c[0]), "+f"(c[1]), "+f"(c[2]), "+f"(c[3])
        : "r"(a[0]), "r"(a[1]), "r"(a[2]), "r"(a[3]), "r"(b0), "r"(b1));
}

__device__ __forceinline__ uint32_t pack_h2(float a, float b) {
    __half2 h = __floats2half2_rn(a, b);
    return *reinterpret_cast<uint32_t*>(&h);
}

// --------------------------- dequant ---------------------------------------
// Byte t of word w holds (k=2t lo-nibble, k=2t+1 hi-nibble). byte_perm
// replicates byte t into bytes 0,2; mask+OR builds {1024+n_lo, 1024+16*n_hi};
// exact HSUB2 {1032,1152} then HMUL2 {s, s/16} -> {(n_lo-8)s, (n_hi-8)s}.
__device__ __forceinline__ uint32_t dq_pair(uint32_t w, uint32_t sel, uint32_t mul2u) {
    const uint32_t SUBC = 0x64806408u;  // half2 {1032, 1152}
    uint32_t v = __byte_perm(w, 0, sel);
    uint32_t p = (v & 0x00F0000Fu) | 0x64006400u;
    __half2 h = __hmul2(__hsub2(*reinterpret_cast<__half2*>(&p),
                                *reinterpret_cast<const __half2*>(&SUBC)),
                        *reinterpret_cast<__half2*>(&mul2u));
    return *reinterpret_cast<uint32_t*>(&h);
}

// --------------------------- prefetch fragment ------------------------------

struct Frag {
    uint4  qa, qb;           // 8 qweight words
    float4 xa0, xa1;         // x row (tid>>3),    8 k-values
    float4 xb0, xb1;         // x row (tid>>3)+16
    float  sc;               // scales[c/2][n0+tid]
};

__device__ __forceinline__ Frag load_frag(int c, const uint4* __restrict__ qw4,
                                          const float4* __restrict__ x4,
                                          const float* __restrict__ scales,
                                          int tid, int n0) {
    Frag f;
    int qi = (c * 8 + (tid >> 4)) * (NDIM / 4) + (n0 >> 2) + (tid & 15);
    f.qa = qw4[qi];
    f.qb = qw4[qi + 16];
    int xi = (tid >> 3) * (KDIM / 4) + c * 16 + (tid & 7) * 2;
    f.xa0 = x4[xi];
    f.xa1 = x4[xi + 1];
    f.xb0 = x4[xi + 16 * (KDIM / 4)];
    f.xb1 = x4[xi + 16 * (KDIM / 4) + 1];
    f.sc  = scales[(c >> 1) * NDIM + n0 + tid];
    return f;
}

// --------------------------- main kernel ------------------------------------

__global__ void __launch_bounds__(THREADS)
w4a16_partial_kernel(const float* __restrict__ x,
                     const uint32_t* __restrict__ qweight,
                     const float* __restrict__ scales) {
    __shared__ uint32_t s_qw[2][8 * 128];
    __shared__ __align__(16) uint8_t s_x[2][32 * XSTRIDE];
    __shared__ __half s_sc[2][128];

    const int tid  = threadIdx.x;
    const int lane = tid & 31;
    const int wid  = tid >> 5;
    const int n0   = blockIdx.x * NT;
    const int ks   = blockIdx.y;
    const int c0   = ks * CPS;
    const int t4   = lane & 3;
    const uint32_t sel = 0x4040u + (uint32_t)t4 * 0x0101u;

    int nl[4];
#pragma unroll
    for (int j = 0; j < 4; ++j) nl[j] = wid * 32 + (lane >> 2) + 8 * j;

    const uint4*  qw4 = reinterpret_cast<const uint4*>(qweight);
    const float4* x4  = reinterpret_cast<const float4*>(x);
    const __half one16 = __ushort_as_half(0x2C00);   // 1/16

    uint32_t* qdst = &s_qw[0][(tid >> 4) * 128 + (tid & 15) * 4];
    uint8_t*  xdst = &s_x[0][(tid >> 3) * XSTRIDE + (tid & 7) * 16];
    const uint32_t xm_base = smem_u32(&s_x[0][0]) +
                             (uint32_t)(lane & 15) * XSTRIDE + (uint32_t)(lane >> 4) * 16;

    float acc[2][4][4];
#pragma unroll
    for (int mt = 0; mt < 2; ++mt)
#pragma unroll
        for (int j = 0; j < 4; ++j)
#pragma unroll
            for (int r = 0; r < 4; ++r) acc[mt][j][r] = 0.0f;

    Frag cur = load_frag(c0, qw4, x4, scales, tid, n0);

#pragma unroll 2
    for (int ci = 0; ci < CPS; ++ci) {
        const int buf = ci & 1;
        Frag nxt = load_frag(c0 + ((ci + 1) & (CPS - 1)), qw4, x4, scales, tid, n0);

        uint32_t* qd = qdst + buf * (8 * 128);
        *reinterpret_cast<uint4*>(qd)      = cur.qa;
        *reinterpret_cast<uint4*>(qd + 64) = cur.qb;
        uint8_t* xd = xdst + buf * (32 * XSTRIDE);
        uint4 hx;
        hx.x = pack_h2(cur.xa0.x, cur.xa0.y); hx.y = pack_h2(cur.xa0.z, cur.xa0.w);
        hx.z = pack_h2(cur.xa1.x, cur.xa1.y); hx.w = pack_h2(cur.xa1.z, cur.xa1.w);
        *reinterpret_cast<uint4*>(xd) = hx;
        hx.x = pack_h2(cur.xb0.x, cur.xb0.y); hx.y = pack_h2(cur.xb0.z, cur.xb0.w);
        hx.z = pack_h2(cur.xb1.x, cur.xb1.y); hx.w = pack_h2(cur.xb1.z, cur.xb1.w);
        *reinterpret_cast<uint4*>(xd + 16 * XSTRIDE) = hx;
        s_sc[buf][tid] = __float2half(cur.sc);
        __syncthreads();

        uint32_t mul2[4];
#pragma unroll
        for (int j = 0; j < 4; ++j) {
            __half s = s_sc[buf][nl[j]];
            __half2 m = __halves2half2(s, __hmul(s, one16));
            mul2[j] = *reinterpret_cast<uint32_t*>(&m);
        }

        const uint32_t* qs = &s_qw[buf][0];
        const uint32_t xb = xm_base + (uint32_t)buf * (32 * XSTRIDE);

#pragma unroll
        for (int s4 = 0; s4 < 4; ++s4) {
            uint32_t a0[4], a1[4];
            ldmatrix_x4(a0, xb + s4 * 32);
            ldmatrix_x4(a1, xb + s4 * 32 + 16 * XSTRIDE);
#pragma unroll
            for (int j = 0; j < 4; ++j) {
                uint32_t w0 = qs[(2 * s4)     * 128 + nl[j]];
                uint32_t w1 = qs[(2 * s4 + 1) * 128 + nl[j]];
                uint32_t b0 = dq_pair(w0, sel, mul2[j]);
                uint32_t b1 = dq_pair(w1, sel, mul2[j]);
                mma_16816(acc[0][j], a0, b0, b1);
                mma_16816(acc[1][j], a1, b0, b1);
            }
        }
        __syncthreads();
        cur = nxt;
    }

    // partial epilogue: raw f32 sums to scratch[ks][m][n]
    float* sp = g_scratch + ks * (MDIM * NDIM);
#pragma unroll
    for (int j = 0; j < 4; ++j) {
        const int n = n0 + wid * 32 + j * 8 + 2 * t4;
#pragma unroll
        for (int mt = 0; mt < 2; ++mt) {
            const int m0 = mt * 16 + (lane >> 2);
            float2 v01 = { acc[mt][j][0], acc[mt][j][1] };
            float2 v23 = { acc[mt][j][2], acc[mt][j][3] };
            *reinterpret_cast<float2*>(sp + m0 * NDIM + n)       = v01;
            *reinterpret_cast<float2*>(sp + (m0 + 8) * NDIM + n) = v23;
        }
    }
}

// --------------------------- reduce kernel ----------------------------------
// Sum KSPLIT partials (f32), round dot to fp16, add fp16 bias, store f32.

__global__ void __launch_bounds__(256)
w4a16_reduce_kernel(const float* __restrict__ bias, float* __restrict__ out) {
    const int idx = blockIdx.x * 256 + threadIdx.x;     // float2 index
    constexpr int TOT2 = MDIM * NDIM / 2;
    if (idx >= TOT2) return;
    const float2* sp = reinterpret_cast<const float2*>(g_scratch);
    float2 s = sp[idx];
#pragma unroll
    for (int k = 1; k < KSPLIT; ++k) {
        float2 t = sp[idx + k * TOT2];
        s.x += t.x; s.y += t.y;
    }
    const float2 b = reinterpret_cast<const float2*>(bias)[idx % (NDIM / 2)];
    float2 r;
    r.x = __half2float(__hadd(__float2half(s.x), __float2half(b.x)));
    r.y = __half2float(__hadd(__float2half(s.y), __float2half(b.y)));
    reinterpret_cast<float2*>(out)[idx] = r;
}

// --------------------------- launch ------------------------------------------

extern "C" void kernel_launch(void* const* d_in, const int* in_sizes, int n_in,
                              void* d_out, int out_size) {
    (void)out_size;
    const float*    x    = nullptr;   // 262144
    const uint32_t* qw   = nullptr;   // 29360128
    const float*    sc   = nullptr;   // 1835008
    const float*    bias = nullptr;   // 28672
    for (int i = 0; i < n_in; ++i) {
        switch (in_sizes[i]) {
            case MDIM * KDIM:            x    = (const float*)d_in[i];    break;
            case (KDIM / 8) * NDIM:      qw   = (const uint32_t*)d_in[i]; break;
            case (KDIM / 128) * NDIM:    sc   = (const float*)d_in[i];    break;
            case NDIM:                   bias = (const float*)d_in[i];    break;
            default: break;
        }
    }
    float* out = (float*)d_out;

    dim3 grid1(NDIM / NT, KSPLIT);          // (224, 8) = 1792 CTAs
    w4a16_partial_kernel<<<grid1, THREADS>>>(x, qw, sc);

    const int tot2 = MDIM * NDIM / 2;
    w4a16_reduce_kernel<<<(tot2 + 255) / 256, 256>>>(bias, out);
}